// round 3
// baseline (speedup 1.0000x reference)
#include <cuda_runtime.h>
#include <math.h>

#define B_  2
#define N_  1024
#define M_  1024
#define C_  1024
#define H_  16
#define S_  8
#define P_  4
#define HD_ 64

// scale/P = (1/sqrt(8))/4
#define QW_BASE 0.088388347648318447f

// ---------------- device scratch (statics: allocation-free rule) ----------------
__device__ float g_Qw[B_ * N_ * C_];
__device__ float g_K [B_ * M_ * C_];
__device__ float g_V [B_ * M_ * C_];
__device__ float g_AO[B_ * N_ * C_];
__device__ float g_rowmax[B_ * H_ * N_];
__device__ float g_rowsum[B_ * H_ * N_];
// fallback in case d_out does not contain the probs region
__device__ float g_probs_fb[(size_t)B_ * H_ * N_ * M_];

// ---------------- SGEMM: C = A[MxK] @ B[KxN] + bias, optional Q-weight epilogue ----
// BM=BN=128, BK=16, 256 threads, 8x8 per thread.
__global__ __launch_bounds__(256) void sgemm_k(
    const float* __restrict__ A, const float* __restrict__ Bm,
    const float* __restrict__ bias, float* __restrict__ Cm,
    int M, int N, int K, int epi, const float* __restrict__ lamlog)
{
    __shared__ __align__(16) float As[16][128];
    __shared__ __align__(16) float Bs[16][128];

    const int tid  = threadIdx.x;
    const int row0 = blockIdx.y * 128;
    const int col0 = blockIdx.x * 128;
    const int tr   = tid >> 4;   // 0..15
    const int tc   = tid & 15;   // 0..15

    float acc[8][8];
#pragma unroll
    for (int i = 0; i < 8; i++)
#pragma unroll
        for (int j = 0; j < 8; j++) acc[i][j] = 0.0f;

    for (int k0 = 0; k0 < K; k0 += 16) {
        // load A tile 128x16, store transposed As[k][row]
#pragma unroll
        for (int i = 0; i < 2; i++) {
            int t   = tid * 2 + i;        // 0..511
            int ar  = t >> 2;             // 0..127
            int ac4 = t & 3;              // 0..3
            float4 v = *reinterpret_cast<const float4*>(
                A + (size_t)(row0 + ar) * K + k0 + ac4 * 4);
            As[ac4 * 4 + 0][ar] = v.x;
            As[ac4 * 4 + 1][ar] = v.y;
            As[ac4 * 4 + 2][ar] = v.z;
            As[ac4 * 4 + 3][ar] = v.w;
        }
        // load B tile 16x128
#pragma unroll
        for (int i = 0; i < 2; i++) {
            int t   = tid * 2 + i;
            int br  = t >> 5;             // 0..15
            int bc4 = t & 31;             // 0..31
            *reinterpret_cast<float4*>(&Bs[br][bc4 * 4]) =
                *reinterpret_cast<const float4*>(
                    Bm + (size_t)(k0 + br) * N + col0 + bc4 * 4);
        }
        __syncthreads();

#pragma unroll
        for (int k = 0; k < 16; k++) {
            float4 a0 = *reinterpret_cast<float4*>(&As[k][tr * 8]);
            float4 a1 = *reinterpret_cast<float4*>(&As[k][tr * 8 + 4]);
            float4 b0 = *reinterpret_cast<float4*>(&Bs[k][tc * 8]);
            float4 b1 = *reinterpret_cast<float4*>(&Bs[k][tc * 8 + 4]);
            float a[8] = {a0.x, a0.y, a0.z, a0.w, a1.x, a1.y, a1.z, a1.w};
            float b[8] = {b0.x, b0.y, b0.z, b0.w, b1.x, b1.y, b1.z, b1.w};
#pragma unroll
            for (int x = 0; x < 8; x++)
#pragma unroll
                for (int y = 0; y < 8; y++)
                    acc[x][y] = fmaf(a[x], b[y], acc[x][y]);
        }
        __syncthreads();
    }

    // epilogue
#pragma unroll
    for (int x = 0; x < 8; x++) {
        int r = row0 + tr * 8 + x;
#pragma unroll
        for (int y = 0; y < 8; y += 4) {
            float4 v;
            float* pv = &v.x;
#pragma unroll
            for (int j = 0; j < 4; j++) {
                int c = col0 + tc * 8 + y + j;
                float val = acc[x][y + j] + bias[c];
                if (epi == 1) {
                    int h = c >> 6;
                    int s = (c >> 3) & 7;
                    int p = s >> 1;
                    float w = (s & 1) ? (-QW_BASE * expf(lamlog[h * P_ + p]))
                                      : QW_BASE;
                    val *= w;
                }
                pv[j] = val;
            }
            *reinterpret_cast<float4*>(Cm + (size_t)r * N + col0 + tc * 8 + y) = v;
        }
    }
}

// ---------------- QK^T: logits[b,h,n,m] = sum_d Qw[b,n,h*64+d] * K[b,m,h*64+d] ----
// One block per (b,h,ntile-of-64); loops all m-tiles; Q tile stays resident.
__global__ __launch_bounds__(256) void qk_k(float* __restrict__ logits)
{
    __shared__ __align__(16) float Qs[64][64];  // [k][n]
    __shared__ __align__(16) float Ks[64][64];  // [k][m]

    const int tid = threadIdx.x;
    const int nt = blockIdx.x, h = blockIdx.y, b = blockIdx.z;
    const int n0 = nt * 64;
    const int tr = tid >> 4, tc = tid & 15;

    // load Q tile transposed
#pragma unroll
    for (int i = 0; i < 4; i++) {
        int t = tid + i * 256;
        int r = t >> 4, c4 = t & 15;
        float4 v = *reinterpret_cast<const float4*>(
            g_Qw + (size_t)(b * N_ + n0 + r) * C_ + h * 64 + c4 * 4);
        Qs[c4 * 4 + 0][r] = v.x;
        Qs[c4 * 4 + 1][r] = v.y;
        Qs[c4 * 4 + 2][r] = v.z;
        Qs[c4 * 4 + 3][r] = v.w;
    }

    for (int mt = 0; mt < M_ / 64; mt++) {
        int m0 = mt * 64;
        __syncthreads();  // first iter: covers Qs; later: protects Ks reuse
#pragma unroll
        for (int i = 0; i < 4; i++) {
            int t = tid + i * 256;
            int r = t >> 4, c4 = t & 15;
            float4 v = *reinterpret_cast<const float4*>(
                g_K + (size_t)(b * M_ + m0 + r) * C_ + h * 64 + c4 * 4);
            Ks[c4 * 4 + 0][r] = v.x;
            Ks[c4 * 4 + 1][r] = v.y;
            Ks[c4 * 4 + 2][r] = v.z;
            Ks[c4 * 4 + 3][r] = v.w;
        }
        __syncthreads();

        float acc[4][4] = {};
#pragma unroll
        for (int k = 0; k < 64; k++) {
            float4 aq = *reinterpret_cast<float4*>(&Qs[k][tr * 4]);
            float4 bk = *reinterpret_cast<float4*>(&Ks[k][tc * 4]);
            float a[4] = {aq.x, aq.y, aq.z, aq.w};
            float c[4] = {bk.x, bk.y, bk.z, bk.w};
#pragma unroll
            for (int x = 0; x < 4; x++)
#pragma unroll
                for (int y = 0; y < 4; y++)
                    acc[x][y] = fmaf(a[x], c[y], acc[x][y]);
        }

        size_t base = ((size_t)(b * H_ + h) * N_ + n0) * M_ + m0;
#pragma unroll
        for (int x = 0; x < 4; x++) {
            *reinterpret_cast<float4*>(logits + base + (size_t)(tr * 4 + x) * M_ + tc * 4) =
                make_float4(acc[x][0], acc[x][1], acc[x][2], acc[x][3]);
        }
    }
}

// ---------------- per-row max & sum(exp) over M=1024 (one warp per row) ----------
__global__ __launch_bounds__(256) void rowstats_k(
    const float* __restrict__ logits,
    float* __restrict__ rowmax, float* __restrict__ rowsum)
{
    int warp = threadIdx.x >> 5, lane = threadIdx.x & 31;
    int row = blockIdx.x * 8 + warp;  // row in [0, B*H*N)
    const float* p = logits + (size_t)row * M_;

    float4 v[8];
    float mx = -1e30f;
#pragma unroll
    for (int i = 0; i < 8; i++) {
        v[i] = *reinterpret_cast<const float4*>(p + (i * 32 + lane) * 4);
        mx = fmaxf(mx, fmaxf(fmaxf(v[i].x, v[i].y), fmaxf(v[i].z, v[i].w)));
    }
#pragma unroll
    for (int o = 16; o > 0; o >>= 1)
        mx = fmaxf(mx, __shfl_xor_sync(0xffffffffu, mx, o));

    float sum = 0.0f;
#pragma unroll
    for (int i = 0; i < 8; i++) {
        sum += expf(v[i].x - mx) + expf(v[i].y - mx) +
               expf(v[i].z - mx) + expf(v[i].w - mx);
    }
#pragma unroll
    for (int o = 16; o > 0; o >>= 1)
        sum += __shfl_xor_sync(0xffffffffu, sum, o);

    if (lane == 0) {
        rowmax[row] = mx;
        rowsum[row] = sum;
    }
}

// ---------------- P@V: normalize probs in place + accumulate attn_out -------------
__global__ __launch_bounds__(256) void av_k(
    float* __restrict__ probs,
    const float* __restrict__ rowmax, const float* __restrict__ rowsum)
{
    __shared__ __align__(16) float Ps[64][64];  // [m][n]
    __shared__ __align__(16) float Vs[64][64];  // [m][d]

    const int tid = threadIdx.x;
    const int nt = blockIdx.x, h = blockIdx.y, b = blockIdx.z;
    const int n0 = nt * 64;
    const int tr = tid >> 4, tc = tid & 15;

    // each thread handles 4 staging rows; their (mx, 1/sum) are loop-invariant
    float mxr[4], isr[4];
#pragma unroll
    for (int i = 0; i < 4; i++) {
        int r = ((tid + i * 256) >> 4);
        int grow = (b * H_ + h) * N_ + n0 + r;
        mxr[i] = __ldg(rowmax + grow);
        isr[i] = 1.0f / __ldg(rowsum + grow);
    }

    float acc[4][4] = {};

    for (int mt = 0; mt < M_ / 64; mt++) {
        int m0 = mt * 64;
        __syncthreads();
        // load logits tile, normalize, write back probs, stage transposed
#pragma unroll
        for (int i = 0; i < 4; i++) {
            int t = tid + i * 256;
            int r = t >> 4, c4 = t & 15;
            int grow = (b * H_ + h) * N_ + n0 + r;
            size_t idx = (size_t)grow * M_ + m0 + c4 * 4;
            float4 v = *reinterpret_cast<float4*>(probs + idx);
            float mxv = mxr[i];
            float isv = isr[i];
            v.x = __expf(v.x - mxv) * isv;
            v.y = __expf(v.y - mxv) * isv;
            v.z = __expf(v.z - mxv) * isv;
            v.w = __expf(v.w - mxv) * isv;
            *reinterpret_cast<float4*>(probs + idx) = v;
            Ps[c4 * 4 + 0][r] = v.x;
            Ps[c4 * 4 + 1][r] = v.y;
            Ps[c4 * 4 + 2][r] = v.z;
            Ps[c4 * 4 + 3][r] = v.w;
        }
        // load V tile
#pragma unroll
        for (int i = 0; i < 4; i++) {
            int t = tid + i * 256;
            int r = t >> 4, c4 = t & 15;
            *reinterpret_cast<float4*>(&Vs[r][c4 * 4]) =
                *reinterpret_cast<const float4*>(
                    g_V + (size_t)(b * M_ + m0 + r) * C_ + h * 64 + c4 * 4);
        }
        __syncthreads();

#pragma unroll
        for (int k = 0; k < 64; k++) {
            float4 ap = *reinterpret_cast<float4*>(&Ps[k][tr * 4]);
            float4 av = *reinterpret_cast<float4*>(&Vs[k][tc * 4]);
            float a[4] = {ap.x, ap.y, ap.z, ap.w};
            float c[4] = {av.x, av.y, av.z, av.w};
#pragma unroll
            for (int x = 0; x < 4; x++)
#pragma unroll
                for (int y = 0; y < 4; y++)
                    acc[x][y] = fmaf(a[x], c[y], acc[x][y]);
        }
    }

#pragma unroll
    for (int x = 0; x < 4; x++) {
        *reinterpret_cast<float4*>(
            g_AO + (size_t)(b * N_ + n0 + tr * 4 + x) * C_ + h * 64 + tc * 4) =
            make_float4(acc[x][0], acc[x][1], acc[x][2], acc[x][3]);
    }
}

// ---------------------------------- host ----------------------------------------
extern "C" void kernel_launch(void* const* d_in, const int* in_sizes, int n_in,
                              void* d_out, int out_size)
{
    const float* query  = (const float*)d_in[0];
    const float* key    = (const float*)d_in[1];
    const float* value  = (const float*)d_in[2];
    const float* Wq     = (const float*)d_in[3];
    const float* bq     = (const float*)d_in[4];
    const float* Wk     = (const float*)d_in[5];
    const float* bk     = (const float*)d_in[6];
    const float* Wv     = (const float*)d_in[7];
    const float* bv     = (const float*)d_in[8];
    const float* Wo     = (const float*)d_in[9];
    const float* bo     = (const float*)d_in[10];
    const float* lamlog = (const float*)d_in[11];
    float* out = (float*)d_out;

    float *qw, *kb, *vb, *ao, *pfb, *rmx, *rsm;
    cudaGetSymbolAddress((void**)&qw,  g_Qw);
    cudaGetSymbolAddress((void**)&kb,  g_K);
    cudaGetSymbolAddress((void**)&vb,  g_V);
    cudaGetSymbolAddress((void**)&ao,  g_AO);
    cudaGetSymbolAddress((void**)&pfb, g_probs_fb);
    cudaGetSymbolAddress((void**)&rmx, g_rowmax);
    cudaGetSymbolAddress((void**)&rsm, g_rowsum);

    const size_t out_elems  = (size_t)B_ * N_ * C_;
    const size_t prob_elems = (size_t)B_ * H_ * N_ * M_;
    float* probs = ((size_t)out_size >= out_elems + prob_elems)
                       ? (out + out_elems) : pfb;

    dim3 gproj(C_ / 128, (B_ * N_) / 128);  // (8, 16)

    // Q' = (query @ Wq + bq) * w_col(lambda);  K, V projections
    sgemm_k<<<gproj, 256>>>(query, Wq, bq, qw, B_ * N_, C_, C_, 1, lamlog);
    sgemm_k<<<gproj, 256>>>(key,   Wk, bk, kb, B_ * M_, C_, C_, 0, nullptr);
    sgemm_k<<<gproj, 256>>>(value, Wv, bv, vb, B_ * M_, C_, C_, 0, nullptr);

    // avg_logits = Q' K^T  (staged into probs region)
    qk_k<<<dim3(N_ / 64, H_, B_), 256>>>(probs);

    // softmax row stats
    rowstats_k<<<(B_ * H_ * N_) / 8, 256>>>(probs, rmx, rsm);

    // normalize probs in place + attn_out = P @ V
    av_k<<<dim3(N_ / 64, H_, B_), 256>>>(probs, rmx, rsm);

    // output = attn_out @ Wo + bo
    sgemm_k<<<gproj, 256>>>(ao, Wo, bo, out, B_ * N_, C_, C_, 0, nullptr);
}

// round 5
// speedup vs baseline: 2.2512x; 2.2512x over previous
#include <cuda_runtime.h>
#include <math.h>
#include <stdint.h>

#define B_  2
#define N_  1024
#define M_  1024
#define C_  1024
#define H_  16
#define P_  4

// scale/P = (1/sqrt(8))/4
#define QW_BASE 0.088388347648318447f

// ---------------- device scratch (statics: allocation-free rule) ----------------
__device__ float g_Qw[B_ * N_ * C_];
__device__ float g_K [B_ * M_ * C_];
__device__ float g_V [B_ * M_ * C_];
__device__ float g_AO[B_ * N_ * C_];
__device__ float g_rowmax[B_ * H_ * N_];
__device__ float g_rowsum[B_ * H_ * N_];
__device__ float g_probs_fb[(size_t)B_ * H_ * N_ * M_];

// ---------------- tf32 helpers ---------------------------------------------------
__device__ __forceinline__ uint32_t f2tf(float x) {
    uint32_t r;
    asm("cvt.rna.tf32.f32 %0, %1;" : "=r"(r) : "f"(x));
    return r;
}
__device__ __forceinline__ void mma8(float* c, const uint32_t* a, const uint32_t* b) {
    asm volatile(
        "mma.sync.aligned.m16n8k8.row.col.f32.tf32.tf32.f32 "
        "{%0,%1,%2,%3},{%4,%5,%6,%7},{%8,%9},{%0,%1,%2,%3};"
        : "+f"(c[0]), "+f"(c[1]), "+f"(c[2]), "+f"(c[3])
        : "r"(a[0]), "r"(a[1]), "r"(a[2]), "r"(a[3]), "r"(b[0]), "r"(b[1]));
}

// ---------------- TF32 GEMM: C = A[MxK] @ B[KxN] + bias (+ Q-weight epilogue) -----
// BM=BN=128, BK=16, 256 threads (8 warps, 2m x 4n), warp tile 64x32.
__global__ __launch_bounds__(256) void sgemm_tc(
    const float* __restrict__ A, const float* __restrict__ Bm,
    const float* __restrict__ bias, float* __restrict__ Cm,
    int M, int N, int K, int epi, const float* __restrict__ lamlog)
{
    __shared__ uint32_t As[128][20];   // [m][k], stride 20 (bank-safe: 20*grp+t4)
    __shared__ uint32_t Bs[16][136];   // [k][n], stride 136 (bank-safe: 8*t4+grp)

    const int tid  = threadIdx.x;
    const int warp = tid >> 5, lane = tid & 31;
    const int grp  = lane >> 2, t4 = lane & 3;
    const int wm   = warp >> 2;      // 0..1 -> 64 rows
    const int wn   = warp & 3;       // 0..3 -> 32 cols
    const int row0 = blockIdx.y * 128;
    const int col0 = blockIdx.x * 128;

    float acc[4][4][4] = {};

    for (int k0 = 0; k0 < K; k0 += 16) {
        // stage A tile 128x16 (row-major, cvt to tf32)
#pragma unroll
        for (int i = 0; i < 2; i++) {
            int t  = tid * 2 + i;
            int ar = t >> 2, ac4 = t & 3;
            float4 v = *reinterpret_cast<const float4*>(
                A + (size_t)(row0 + ar) * K + k0 + ac4 * 4);
            As[ar][ac4 * 4 + 0] = f2tf(v.x);
            As[ar][ac4 * 4 + 1] = f2tf(v.y);
            As[ar][ac4 * 4 + 2] = f2tf(v.z);
            As[ar][ac4 * 4 + 3] = f2tf(v.w);
        }
        // stage B tile 16x128
#pragma unroll
        for (int i = 0; i < 2; i++) {
            int t  = tid * 2 + i;
            int br = t >> 5, bc4 = t & 31;
            float4 v = *reinterpret_cast<const float4*>(
                Bm + (size_t)(k0 + br) * N + col0 + bc4 * 4);
            Bs[br][bc4 * 4 + 0] = f2tf(v.x);
            Bs[br][bc4 * 4 + 1] = f2tf(v.y);
            Bs[br][bc4 * 4 + 2] = f2tf(v.z);
            Bs[br][bc4 * 4 + 3] = f2tf(v.w);
        }
        __syncthreads();

#pragma unroll
        for (int ks = 0; ks < 16; ks += 8) {
            uint32_t a[4][4], b[4][2];
#pragma unroll
            for (int i = 0; i < 4; i++) {
                int mb = wm * 64 + i * 16;
                a[i][0] = As[mb + grp][ks + t4];
                a[i][1] = As[mb + 8 + grp][ks + t4];
                a[i][2] = As[mb + grp][ks + 4 + t4];
                a[i][3] = As[mb + 8 + grp][ks + 4 + t4];
            }
#pragma unroll
            for (int j = 0; j < 4; j++) {
                int nb = wn * 32 + j * 8;
                b[j][0] = Bs[ks + t4][nb + grp];
                b[j][1] = Bs[ks + 4 + t4][nb + grp];
            }
#pragma unroll
            for (int i = 0; i < 4; i++)
#pragma unroll
                for (int j = 0; j < 4; j++)
                    mma8(acc[i][j], a[i], b[j]);
        }
        __syncthreads();
    }

    // epilogue: per-j column weight (each j covers one 8-col signal block)
    float wj[4];
#pragma unroll
    for (int j = 0; j < 4; j++) {
        if (epi) {
            int cb = col0 + wn * 32 + j * 8;
            int h = cb >> 6, s = (cb >> 3) & 7, p = s >> 1;
            wj[j] = (s & 1) ? (-QW_BASE * expf(lamlog[h * P_ + p])) : QW_BASE;
        } else {
            wj[j] = 1.0f;
        }
    }
#pragma unroll
    for (int i = 0; i < 4; i++) {
        int r0 = row0 + wm * 64 + i * 16 + grp;
#pragma unroll
        for (int j = 0; j < 4; j++) {
            int c = col0 + wn * 32 + j * 8 + 2 * t4;
            float b0 = bias[c], b1 = bias[c + 1];
            float2 v0 = make_float2((acc[i][j][0] + b0) * wj[j],
                                    (acc[i][j][1] + b1) * wj[j]);
            float2 v1 = make_float2((acc[i][j][2] + b0) * wj[j],
                                    (acc[i][j][3] + b1) * wj[j]);
            *reinterpret_cast<float2*>(Cm + (size_t)r0 * N + c)       = v0;
            *reinterpret_cast<float2*>(Cm + (size_t)(r0 + 8) * N + c) = v1;
        }
    }
}

// ---------------- QK^T (TF32 MMA): logits[b,h,n,m] = sum_d Qw.K -------------------
// Block: n-tile 64, loops m in 64-chunks. 8 warps as 2(n) x 4(m), warp 32x16.
__global__ __launch_bounds__(256) void qk_tc(float* __restrict__ logits)
{
    __shared__ uint32_t Qs[64][68];  // [n][d]
    __shared__ uint32_t Ks[64][68];  // [m][d]  (B frag reads it as K^T directly)

    const int tid  = threadIdx.x;
    const int warp = tid >> 5, lane = tid & 31;
    const int grp  = lane >> 2, t4 = lane & 3;
    const int wi   = warp >> 2;   // n: 0..1 (x32)
    const int wj   = warp & 3;    // m: 0..3 (x16)
    const int nt = blockIdx.x, h = blockIdx.y, b = blockIdx.z;
    const int n0 = nt * 64;

    // stage Q tile 64x64
#pragma unroll
    for (int i = 0; i < 4; i++) {
        int t = tid + i * 256;
        int r = t >> 4, c4 = t & 15;
        float4 v = *reinterpret_cast<const float4*>(
            g_Qw + (size_t)(b * N_ + n0 + r) * C_ + h * 64 + c4 * 4);
        Qs[r][c4 * 4 + 0] = f2tf(v.x);
        Qs[r][c4 * 4 + 1] = f2tf(v.y);
        Qs[r][c4 * 4 + 2] = f2tf(v.z);
        Qs[r][c4 * 4 + 3] = f2tf(v.w);
    }

    for (int mt = 0; mt < M_ / 64; mt++) {
        int m0 = mt * 64;
        __syncthreads();
#pragma unroll
        for (int i = 0; i < 4; i++) {
            int t = tid + i * 256;
            int r = t >> 4, c4 = t & 15;
            float4 v = *reinterpret_cast<const float4*>(
                g_K + (size_t)(b * M_ + m0 + r) * C_ + h * 64 + c4 * 4);
            Ks[r][c4 * 4 + 0] = f2tf(v.x);
            Ks[r][c4 * 4 + 1] = f2tf(v.y);
            Ks[r][c4 * 4 + 2] = f2tf(v.z);
            Ks[r][c4 * 4 + 3] = f2tf(v.w);
        }
        __syncthreads();

        float acc[2][2][4] = {};
#pragma unroll
        for (int ks = 0; ks < 64; ks += 8) {
            uint32_t a[2][4], bb[2][2];
#pragma unroll
            for (int i = 0; i < 2; i++) {
                int nb = wi * 32 + i * 16;
                a[i][0] = Qs[nb + grp][ks + t4];
                a[i][1] = Qs[nb + 8 + grp][ks + t4];
                a[i][2] = Qs[nb + grp][ks + 4 + t4];
                a[i][3] = Qs[nb + 8 + grp][ks + 4 + t4];
            }
#pragma unroll
            for (int j = 0; j < 2; j++) {
                int mb = wj * 16 + j * 8;
                bb[j][0] = Ks[mb + grp][ks + t4];
                bb[j][1] = Ks[mb + grp][ks + 4 + t4];
            }
#pragma unroll
            for (int i = 0; i < 2; i++)
#pragma unroll
                for (int j = 0; j < 2; j++)
                    mma8(acc[i][j], a[i], bb[j]);
        }

        size_t rowbase = (size_t)((b * H_ + h) * N_ + n0);
#pragma unroll
        for (int i = 0; i < 2; i++) {
            int r0 = wi * 32 + i * 16 + grp;
#pragma unroll
            for (int j = 0; j < 2; j++) {
                int c = m0 + wj * 16 + j * 8 + 2 * t4;
                *reinterpret_cast<float2*>(logits + (rowbase + r0) * M_ + c) =
                    make_float2(acc[i][j][0], acc[i][j][1]);
                *reinterpret_cast<float2*>(logits + (rowbase + r0 + 8) * M_ + c) =
                    make_float2(acc[i][j][2], acc[i][j][3]);
            }
        }
    }
}

// ---------------- per-row max & sum(exp) over M=1024 (one warp per row) ----------
__global__ __launch_bounds__(256) void rowstats_k(
    const float* __restrict__ logits,
    float* __restrict__ rowmax, float* __restrict__ rowsum)
{
    int warp = threadIdx.x >> 5, lane = threadIdx.x & 31;
    int row = blockIdx.x * 8 + warp;
    const float* p = logits + (size_t)row * M_;

    float4 v[8];
    float mx = -1e30f;
#pragma unroll
    for (int i = 0; i < 8; i++) {
        v[i] = *reinterpret_cast<const float4*>(p + (i * 32 + lane) * 4);
        mx = fmaxf(mx, fmaxf(fmaxf(v[i].x, v[i].y), fmaxf(v[i].z, v[i].w)));
    }
#pragma unroll
    for (int o = 16; o > 0; o >>= 1)
        mx = fmaxf(mx, __shfl_xor_sync(0xffffffffu, mx, o));

    float sum = 0.0f;
#pragma unroll
    for (int i = 0; i < 8; i++) {
        sum += expf(v[i].x - mx) + expf(v[i].y - mx) +
               expf(v[i].z - mx) + expf(v[i].w - mx);
    }
#pragma unroll
    for (int o = 16; o > 0; o >>= 1)
        sum += __shfl_xor_sync(0xffffffffu, sum, o);

    if (lane == 0) {
        rowmax[row] = mx;
        rowsum[row] = sum;
    }
}

// ---------------- P@V (TF32 MMA): normalize probs in place + attn_out -------------
// Block: n-tile 64 x d=64 output, k loops over m in 64-chunks.
__global__ __launch_bounds__(256) void av_tc(
    float* __restrict__ probs,
    const float* __restrict__ rowmax, const float* __restrict__ rowsum)
{
    __shared__ uint32_t Ps[64][68];  // [n][m]
    __shared__ uint32_t Vs[64][72];  // [m][d]

    const int tid  = threadIdx.x;
    const int warp = tid >> 5, lane = tid & 31;
    const int grp  = lane >> 2, t4 = lane & 3;
    const int wi   = warp >> 2;   // n: 0..1 (x32)
    const int wj   = warp & 3;    // d: 0..3 (x16)
    const int nt = blockIdx.x, h = blockIdx.y, b = blockIdx.z;
    const int n0 = nt * 64;

    float mxr[4], isr[4];
#pragma unroll
    for (int i = 0; i < 4; i++) {
        int r = ((tid + i * 256) >> 4);
        int grow = (b * H_ + h) * N_ + n0 + r;
        mxr[i] = __ldg(rowmax + grow);
        isr[i] = 1.0f / __ldg(rowsum + grow);
    }

    float acc[2][2][4] = {};

    for (int mt = 0; mt < M_ / 64; mt++) {
        int m0 = mt * 64;
        __syncthreads();
        // normalize logits tile -> probs (fp32 out) + stage tf32
#pragma unroll
        for (int i = 0; i < 4; i++) {
            int t = tid + i * 256;
            int r = t >> 4, c4 = t & 15;
            int grow = (b * H_ + h) * N_ + n0 + r;
            size_t idx = (size_t)grow * M_ + m0 + c4 * 4;
            float4 v = *reinterpret_cast<float4*>(probs + idx);
            v.x = __expf(v.x - mxr[i]) * isr[i];
            v.y = __expf(v.y - mxr[i]) * isr[i];
            v.z = __expf(v.z - mxr[i]) * isr[i];
            v.w = __expf(v.w - mxr[i]) * isr[i];
            *reinterpret_cast<float4*>(probs + idx) = v;
            Ps[r][c4 * 4 + 0] = f2tf(v.x);
            Ps[r][c4 * 4 + 1] = f2tf(v.y);
            Ps[r][c4 * 4 + 2] = f2tf(v.z);
            Ps[r][c4 * 4 + 3] = f2tf(v.w);
        }
        // stage V tile [m][d]
#pragma unroll
        for (int i = 0; i < 4; i++) {
            int t = tid + i * 256;
            int r = t >> 4, c4 = t & 15;
            float4 v = *reinterpret_cast<const float4*>(
                g_V + (size_t)(b * M_ + m0 + r) * C_ + h * 64 + c4 * 4);
            Vs[r][c4 * 4 + 0] = f2tf(v.x);
            Vs[r][c4 * 4 + 1] = f2tf(v.y);
            Vs[r][c4 * 4 + 2] = f2tf(v.z);
            Vs[r][c4 * 4 + 3] = f2tf(v.w);
        }
        __syncthreads();

#pragma unroll
        for (int ks = 0; ks < 64; ks += 8) {
            uint32_t a[2][4], bb[2][2];
#pragma unroll
            for (int i = 0; i < 2; i++) {
                int nb = wi * 32 + i * 16;
                a[i][0] = Ps[nb + grp][ks + t4];
                a[i][1] = Ps[nb + 8 + grp][ks + t4];
                a[i][2] = Ps[nb + grp][ks + 4 + t4];
                a[i][3] = Ps[nb + 8 + grp][ks + 4 + t4];
            }
#pragma unroll
            for (int j = 0; j < 2; j++) {
                int db = wj * 16 + j * 8;
                bb[j][0] = Vs[ks + t4][db + grp];
                bb[j][1] = Vs[ks + 4 + t4][db + grp];
            }
#pragma unroll
            for (int i = 0; i < 2; i++)
#pragma unroll
                for (int j = 0; j < 2; j++)
                    mma8(acc[i][j], a[i], bb[j]);
        }
    }

#pragma unroll
    for (int i = 0; i < 2; i++) {
        int r0 = n0 + wi * 32 + i * 16 + grp;
#pragma unroll
        for (int j = 0; j < 2; j++) {
            int d = wj * 16 + j * 8 + 2 * t4;
            *reinterpret_cast<float2*>(
                g_AO + (size_t)(b * N_ + r0) * C_ + h * 64 + d) =
                make_float2(acc[i][j][0], acc[i][j][1]);
            *reinterpret_cast<float2*>(
                g_AO + (size_t)(b * N_ + r0 + 8) * C_ + h * 64 + d) =
                make_float2(acc[i][j][2], acc[i][j][3]);
        }
    }
}

// ---------------------------------- host ----------------------------------------
extern "C" void kernel_launch(void* const* d_in, const int* in_sizes, int n_in,
                              void* d_out, int out_size)
{
    const float* query  = (const float*)d_in[0];
    const float* key    = (const float*)d_in[1];
    const float* value  = (const float*)d_in[2];
    const float* Wq     = (const float*)d_in[3];
    const float* bq     = (const float*)d_in[4];
    const float* Wk     = (const float*)d_in[5];
    const float* bk     = (const float*)d_in[6];
    const float* Wv     = (const float*)d_in[7];
    const float* bv     = (const float*)d_in[8];
    const float* Wo     = (const float*)d_in[9];
    const float* bo     = (const float*)d_in[10];
    const float* lamlog = (const float*)d_in[11];
    float* out = (float*)d_out;

    float *qw, *kb, *vb, *ao, *pfb, *rmx, *rsm;
    cudaGetSymbolAddress((void**)&qw,  g_Qw);
    cudaGetSymbolAddress((void**)&kb,  g_K);
    cudaGetSymbolAddress((void**)&vb,  g_V);
    cudaGetSymbolAddress((void**)&ao,  g_AO);
    cudaGetSymbolAddress((void**)&pfb, g_probs_fb);
    cudaGetSymbolAddress((void**)&rmx, g_rowmax);
    cudaGetSymbolAddress((void**)&rsm, g_rowsum);

    const size_t out_elems  = (size_t)B_ * N_ * C_;
    const size_t prob_elems = (size_t)B_ * H_ * N_ * M_;
    float* probs = ((size_t)out_size >= out_elems + prob_elems)
                       ? (out + out_elems) : pfb;

    dim3 gproj(C_ / 128, (B_ * N_) / 128);  // (8, 16)

    // Q' = (query @ Wq + bq) * w_col(lambda);  K, V projections
    sgemm_tc<<<gproj, 256>>>(query, Wq, bq, qw, B_ * N_, C_, C_, 1, lamlog);
    sgemm_tc<<<gproj, 256>>>(key,   Wk, bk, kb, B_ * M_, C_, C_, 0, nullptr);
    sgemm_tc<<<gproj, 256>>>(value, Wv, bv, vb, B_ * M_, C_, C_, 0, nullptr);

    // avg_logits = Q' K^T  (staged into probs region)
    qk_tc<<<dim3(N_ / 64, H_, B_), 256>>>(probs);

    // softmax row stats
    rowstats_k<<<(B_ * H_ * N_) / 8, 256>>>(probs, rmx, rsm);

    // normalize probs in place + attn_out = P @ V
    av_tc<<<dim3(N_ / 64, H_, B_), 256>>>(probs, rmx, rsm);

    // output = attn_out @ Wo + bo
    sgemm_tc<<<gproj, 256>>>(ao, Wo, bo, out, B_ * N_, C_, C_, 0, nullptr);
}